// round 4
// baseline (speedup 1.0000x reference)
#include <cuda_runtime.h>

#define BATCH  512
#define SEQ    256
#define HID    768
#define NCLS   2
#define NCHUNK 4
#define CHUNK  64   // SEQ / NCHUNK

// Encoded pooled maxima [BATCH*2][HID] as order-preserving uint32 (3 MB).
__device__ unsigned int g_pooledEnc[BATCH * 2 * HID];
// Effective lengths per (batch, half).
__device__ int g_eff[BATCH * 2];

// Monotonic float<->uint mapping: enc(a) < enc(b)  <=>  a < b
__device__ __forceinline__ unsigned int enc_f32(float f) {
    unsigned int u = __float_as_uint(f);
    return (u & 0x80000000u) ? ~u : (u | 0x80000000u);
}
__device__ __forceinline__ float dec_f32(unsigned int u) {
    unsigned int b = (u & 0x80000000u) ? (u ^ 0x80000000u) : ~u;
    return __uint_as_float(b);
}
#define ENC_NEG_INF 0x007fffffu   // enc(-inf)

// One CTA per (batch, half) row: compute eff, init pooled buffer to enc(-inf).
__global__ __launch_bounds__(256) void prep_kernel(
    const int* __restrict__ m1, const int* __restrict__ m2)
{
    const int r = blockIdx.x;          // 0..1023 : r = b*2 + half
    const int t = threadIdx.x;         // 0..255
    const int b    = r >> 1;
    const int half = r & 1;
    const int* __restrict__ m = half ? m2 : m1;

    // first zero index (or SEQ)
    int cand = (m[b * SEQ + t] == 0) ? t : SEQ;
    #pragma unroll
    for (int off = 16; off > 0; off >>= 1)
        cand = min(cand, __shfl_down_sync(0xffffffffu, cand, off));
    __shared__ int s_w[8];
    if ((t & 31) == 0) s_w[t >> 5] = cand;
    __syncthreads();
    if (t == 0) {
        int fz = s_w[0];
        #pragma unroll
        for (int w = 1; w < 8; w++) fz = min(fz, s_w[w]);
        g_eff[r] = (fz == 0 || fz == SEQ) ? SEQ : fz;
    }

    // init pooled row (768 values, 3 per thread)
    unsigned int* __restrict__ p = g_pooledEnc + (size_t)r * HID;
    p[t] = ENC_NEG_INF;
    p[t + 256] = ENC_NEG_INF;
    p[t + 512] = ENC_NEG_INF;
}

// One CTA per (batch, half, s-chunk). 192 threads, each owns one float4.
__global__ __launch_bounds__(192) void pool_kernel(
    const float* __restrict__ x1, const float* __restrict__ x2)
{
    const int b    = blockIdx.x;
    const int half = blockIdx.y;
    const int cz   = blockIdx.z;
    const int t    = threadIdx.x;  // 0..191

    const int eff = g_eff[b * 2 + half];
    const int s_begin = cz * CHUNK;
    const int s_end   = min(eff, s_begin + CHUNK);
    if (s_begin >= s_end) return;          // chunk beyond eff: contributes nothing

    const float* __restrict__ x = half ? x2 : x1;
    const float4* __restrict__ xp =
        reinterpret_cast<const float4*>(x + (size_t)b * SEQ * HID) + t;
    const int STRIDE4 = HID / 4;  // 192 float4 per s-row

    const float NEG = __int_as_float(0xff800000);  // -inf
    float4 a0 = make_float4(NEG, NEG, NEG, NEG);
    float4 a1 = a0, a2 = a0, a3 = a0;

    const int n  = s_end - s_begin;
    const int stop8 = s_begin + (n & ~7);
    int s = s_begin;
    for (; s < stop8; s += 8) {
        float4 v0 = __ldcs(xp + (size_t)(s + 0) * STRIDE4);
        float4 v1 = __ldcs(xp + (size_t)(s + 1) * STRIDE4);
        float4 v2 = __ldcs(xp + (size_t)(s + 2) * STRIDE4);
        float4 v3 = __ldcs(xp + (size_t)(s + 3) * STRIDE4);
        float4 v4 = __ldcs(xp + (size_t)(s + 4) * STRIDE4);
        float4 v5 = __ldcs(xp + (size_t)(s + 5) * STRIDE4);
        float4 v6 = __ldcs(xp + (size_t)(s + 6) * STRIDE4);
        float4 v7 = __ldcs(xp + (size_t)(s + 7) * STRIDE4);
        a0.x = fmaxf(a0.x, fmaxf(v0.x, v4.x)); a0.y = fmaxf(a0.y, fmaxf(v0.y, v4.y));
        a0.z = fmaxf(a0.z, fmaxf(v0.z, v4.z)); a0.w = fmaxf(a0.w, fmaxf(v0.w, v4.w));
        a1.x = fmaxf(a1.x, fmaxf(v1.x, v5.x)); a1.y = fmaxf(a1.y, fmaxf(v1.y, v5.y));
        a1.z = fmaxf(a1.z, fmaxf(v1.z, v5.z)); a1.w = fmaxf(a1.w, fmaxf(v1.w, v5.w));
        a2.x = fmaxf(a2.x, fmaxf(v2.x, v6.x)); a2.y = fmaxf(a2.y, fmaxf(v2.y, v6.y));
        a2.z = fmaxf(a2.z, fmaxf(v2.z, v6.z)); a2.w = fmaxf(a2.w, fmaxf(v2.w, v6.w));
        a3.x = fmaxf(a3.x, fmaxf(v3.x, v7.x)); a3.y = fmaxf(a3.y, fmaxf(v3.y, v7.y));
        a3.z = fmaxf(a3.z, fmaxf(v3.z, v7.z)); a3.w = fmaxf(a3.w, fmaxf(v3.w, v7.w));
    }
    for (; s < s_end; s++) {
        float4 v0 = __ldcs(xp + (size_t)s * STRIDE4);
        a0.x = fmaxf(a0.x, v0.x); a0.y = fmaxf(a0.y, v0.y);
        a0.z = fmaxf(a0.z, v0.z); a0.w = fmaxf(a0.w, v0.w);
    }
    a0.x = fmaxf(fmaxf(a0.x, a1.x), fmaxf(a2.x, a3.x));
    a0.y = fmaxf(fmaxf(a0.y, a1.y), fmaxf(a2.y, a3.y));
    a0.z = fmaxf(fmaxf(a0.z, a1.z), fmaxf(a2.z, a3.z));
    a0.w = fmaxf(fmaxf(a0.w, a1.w), fmaxf(a2.w, a3.w));

    unsigned int* __restrict__ dst =
        g_pooledEnc + (size_t)(b * 2 + half) * HID + t * 4;
    atomicMax(dst + 0, enc_f32(a0.x));
    atomicMax(dst + 1, enc_f32(a0.y));
    atomicMax(dst + 2, enc_f32(a0.z));
    atomicMax(dst + 3, enc_f32(a0.w));
}

// One CTA per batch row: out[b, c] = decode(pooled[b]) . W[c] + bias[c]
// g_pooledEnc viewed as [BATCH][2*HID] matches W's column order directly.
__global__ __launch_bounds__(256) void gemv_kernel(
    const float* __restrict__ W, const float* __restrict__ bias,
    float* __restrict__ out)
{
    const int b = blockIdx.x;
    const int t = threadIdx.x;  // 0..255
    const unsigned int* __restrict__ p = g_pooledEnc + (size_t)b * (2 * HID);

    float acc0 = 0.f, acc1 = 0.f;
    #pragma unroll
    for (int h = t; h < 2 * HID; h += 256) {
        float v = dec_f32(p[h]);
        acc0 += v * W[h];
        acc1 += v * W[2 * HID + h];
    }

    // warp shuffle reduce, then 8 warp partials in shared
    #pragma unroll
    for (int off = 16; off > 0; off >>= 1) {
        acc0 += __shfl_down_sync(0xffffffffu, acc0, off);
        acc1 += __shfl_down_sync(0xffffffffu, acc1, off);
    }
    __shared__ float s0[8], s1[8];
    if ((t & 31) == 0) { s0[t >> 5] = acc0; s1[t >> 5] = acc1; }
    __syncthreads();
    if (t == 0) {
        float r0 = s0[0], r1 = s1[0];
        #pragma unroll
        for (int w = 1; w < 8; w++) { r0 += s0[w]; r1 += s1[w]; }
        out[b * NCLS + 0] = r0 + bias[0];
        out[b * NCLS + 1] = r1 + bias[1];
    }
}

extern "C" void kernel_launch(void* const* d_in, const int* in_sizes, int n_in,
                              void* d_out, int out_size)
{
    const float* x1 = (const float*)d_in[0];
    const float* x2 = (const float*)d_in[1];
    const int*   m1 = (const int*)  d_in[2];
    const int*   m2 = (const int*)  d_in[3];
    const float* W  = (const float*)d_in[4];
    const float* bs = (const float*)d_in[5];
    float* out = (float*)d_out;

    prep_kernel<<<BATCH * 2, 256>>>(m1, m2);
    dim3 grid(BATCH, 2, NCHUNK);
    pool_kernel<<<grid, 192>>>(x1, x2);
    gemv_kernel<<<BATCH, 256>>>(W, bs, out);
}